// round 2
// baseline (speedup 1.0000x reference)
#include <cuda_runtime.h>
#include <cuda_bf16.h>
#include <cstdint>

// ---------------------------------------------------------------------------
// proj scratch: [100000 x 128] fp32 = 51.2 MB static device array (no allocs)
// ---------------------------------------------------------------------------
#define MAX_NODES 100000
#define DIM 128
__device__ float g_proj[(size_t)MAX_NODES * DIM];

// ---------------------------------------------------------------------------
// Kernel 1: proj = relu(h @ W^T)
//   h:    [N, 128] row-major
//   W:    [128, 128] row-major (out, in) -> proj[n][o] = sum_k h[n][k]*W[o][k]
// Classic register-tiled SGEMM: BM=64, BN=128, BK=16, TM=4, TN=8, 256 thr.
// ---------------------------------------------------------------------------
#define BM 64
#define BN 128
#define BK 16
#define TM 4
#define TN 8

__global__ __launch_bounds__(256)
void gemm_relu_kernel(const float* __restrict__ h,
                      const float* __restrict__ W,
                      int N)
{
    __shared__ float As[BK][BM];   // h tile, transposed  [k][row]
    __shared__ float Bs[BK][BN];   // W tile, transposed  [k][col]

    const int tid = threadIdx.x;          // 0..255
    const int tx  = tid & 15;             // col group 0..15  (TN=8 each)
    const int ty  = tid >> 4;             // row group 0..15  (TM=4 each)
    const int rowBase = blockIdx.x * BM;

    float acc[TM][TN];
    #pragma unroll
    for (int i = 0; i < TM; i++)
        #pragma unroll
        for (int j = 0; j < TN; j++)
            acc[i][j] = 0.0f;

    for (int kb = 0; kb < DIM; kb += BK) {
        // --- load A tile: 64 rows x 16 k = 1024 floats, 1 float4 per thread
        {
            int r  = tid >> 2;             // 0..63
            int k4 = (tid & 3) << 2;       // 0,4,8,12
            int gr = rowBase + r;
            float4 v = make_float4(0.f, 0.f, 0.f, 0.f);
            if (gr < N)
                v = *reinterpret_cast<const float4*>(h + (size_t)gr * DIM + kb + k4);
            As[k4 + 0][r] = v.x;
            As[k4 + 1][r] = v.y;
            As[k4 + 2][r] = v.z;
            As[k4 + 3][r] = v.w;
        }
        // --- load B tile: 128 cols x 16 k = 2048 floats, 2 float4 per thread
        #pragma unroll
        for (int i = 0; i < 2; i++) {
            int idx = tid * 2 + i;         // 0..511
            int c   = idx >> 2;            // 0..127
            int k4  = (idx & 3) << 2;      // 0,4,8,12
            float4 v = *reinterpret_cast<const float4*>(W + (size_t)c * DIM + kb + k4);
            Bs[k4 + 0][c] = v.x;
            Bs[k4 + 1][c] = v.y;
            Bs[k4 + 2][c] = v.z;
            Bs[k4 + 3][c] = v.w;
        }
        __syncthreads();

        #pragma unroll
        for (int k = 0; k < BK; k++) {
            float a[TM], b[TN];
            #pragma unroll
            for (int i = 0; i < TM; i++) a[i] = As[k][ty * TM + i];
            #pragma unroll
            for (int j = 0; j < TN; j++) b[j] = Bs[k][tx * TN + j];
            #pragma unroll
            for (int i = 0; i < TM; i++)
                #pragma unroll
                for (int j = 0; j < TN; j++)
                    acc[i][j] = fmaf(a[i], b[j], acc[i][j]);
        }
        __syncthreads();
    }

    // --- store with ReLU
    #pragma unroll
    for (int i = 0; i < TM; i++) {
        int gr = rowBase + ty * TM + i;
        if (gr < N) {
            #pragma unroll
            for (int j = 0; j < TN; j += 4) {
                float4 v;
                v.x = fmaxf(acc[i][j + 0], 0.0f);
                v.y = fmaxf(acc[i][j + 1], 0.0f);
                v.z = fmaxf(acc[i][j + 2], 0.0f);
                v.w = fmaxf(acc[i][j + 3], 0.0f);
                *reinterpret_cast<float4*>(g_proj + (size_t)gr * DIM + tx * TN + j) = v;
            }
        }
    }
}

// ---------------------------------------------------------------------------
// Kernel 2: out[dst[e]] += proj[src[e]]   (128 fp32 per edge)
// One warp per edge; each lane handles one float4 (32 lanes * 4 = 128).
// Uses red.global.add.v4.f32 (sm_90+): no return value, 16B per red op.
// NOTE: indices are int32 (JAX x64 disabled downgrades int64 -> int32).
// ---------------------------------------------------------------------------
__global__ __launch_bounds__(256)
void scatter_kernel(const int* __restrict__ src,
                    const int* __restrict__ dst,
                    float* __restrict__ out,
                    int E)
{
    int gtid = blockIdx.x * blockDim.x + threadIdx.x;
    int e    = gtid >> 5;
    int lane = gtid & 31;
    if (e >= E) return;

    int s = src[e];
    int d = dst[e];

    const float4 v = *reinterpret_cast<const float4*>(
        g_proj + (size_t)s * DIM + lane * 4);
    float* p = out + (size_t)d * DIM + lane * 4;

    asm volatile("red.global.add.v4.f32 [%0], {%1, %2, %3, %4};"
                 :: "l"(p), "f"(v.x), "f"(v.y), "f"(v.z), "f"(v.w)
                 : "memory");
}

// ---------------------------------------------------------------------------
// Launch
//   d_in[0]: h    float32 [N*128]
//   d_in[1]: W    float32 [128*128]
//   d_in[2]: src  int32   [E]
//   d_in[3]: dst  int32   [E]
//   d_out  : float32 [N*128]
// ---------------------------------------------------------------------------
extern "C" void kernel_launch(void* const* d_in, const int* in_sizes, int n_in,
                              void* d_out, int out_size)
{
    const float* h   = (const float*)d_in[0];
    const float* W   = (const float*)d_in[1];
    const int*   src = (const int*)d_in[2];
    const int*   dst = (const int*)d_in[3];
    float*       out = (float*)d_out;

    const int N = in_sizes[0] / DIM;
    const int E = in_sizes[2];

    // out is poisoned; zero it (graph-capturable memset node)
    cudaMemsetAsync(out, 0, (size_t)out_size * sizeof(float), 0);

    // GEMM + ReLU into g_proj
    int gemmBlocks = (N + BM - 1) / BM;
    gemm_relu_kernel<<<gemmBlocks, 256>>>(h, W, N);

    // Edge scatter: one warp per edge
    long long totalThreads = (long long)E * 32;
    int scatterBlocks = (int)((totalThreads + 255) / 256);
    scatter_kernel<<<scatterBlocks, 256>>>(src, dst, out, E);
}

// round 4
// speedup vs baseline: 1.3109x; 1.3109x over previous
#include <cuda_runtime.h>
#include <cuda_bf16.h>
#include <cstdint>

// ---------------------------------------------------------------------------
// proj scratch: [100000 x 128] fp32 = 51.2 MB static device array (no allocs)
// ---------------------------------------------------------------------------
#define MAX_NODES 100000
#define DIM 128
__device__ float g_proj[(size_t)MAX_NODES * DIM];

// ---------------------------------------------------------------------------
// mma.sync bf16 helpers (baseline PTX, works on compute_103 virtual arch)
// ---------------------------------------------------------------------------
__device__ __forceinline__ uint32_t smem_to_u32(const void* smem_ptr) {
    uint32_t addr;
    asm("{ .reg .u64 tmp; cvta.to.shared.u64 tmp, %1; cvt.u32.u64 %0, tmp; }"
        : "=r"(addr) : "l"(smem_ptr));
    return addr;
}

#define LDMATRIX_X4(r0, r1, r2, r3, addr) \
    asm volatile("ldmatrix.sync.aligned.m8n8.x4.shared.b16 {%0,%1,%2,%3}, [%4];" \
        : "=r"(r0), "=r"(r1), "=r"(r2), "=r"(r3) : "r"(addr))

#define MMA_BF16(c, a, b) \
    asm volatile("mma.sync.aligned.m16n8k16.row.col.f32.bf16.bf16.f32 " \
        "{%0,%1,%2,%3}, {%4,%5,%6,%7}, {%8,%9}, {%0,%1,%2,%3};" \
        : "+f"((c)[0]), "+f"((c)[1]), "+f"((c)[2]), "+f"((c)[3]) \
        : "r"((a)[0]), "r"((a)[1]), "r"((a)[2]), "r"((a)[3]), \
          "r"((b)[0]), "r"((b)[1]))

__device__ __forceinline__ uint32_t pack_bf16_hi(float a, float b,
                                                 float& ra, float& rb) {
    __nv_bfloat16 ha = __float2bfloat16(a);
    __nv_bfloat16 hb = __float2bfloat16(b);
    ra = a - __bfloat162float(ha);
    rb = b - __bfloat162float(hb);
    return ((uint32_t)__bfloat16_as_ushort(hb) << 16) | __bfloat16_as_ushort(ha);
}
__device__ __forceinline__ uint32_t pack_bf16(float a, float b) {
    return ((uint32_t)__bfloat16_as_ushort(__float2bfloat16(b)) << 16)
         | __bfloat16_as_ushort(__float2bfloat16(a));
}

// ---------------------------------------------------------------------------
// Kernel 1: proj = relu(h @ W^T), split-bf16 HMMA (3 passes: hh, hl, lh)
//   CTA: 128 rows x 128 out x 128 k. 8 warps = 2(m) x 4(n), warp tile 64x32.
//   smem tiles: A_hi/A_lo [128][136] bf16 (row-major, k contiguous, pad 8),
//               W_hi/W_lo [128][136] bf16 ([out][k], k contiguous = B col-major)
// ---------------------------------------------------------------------------
#define LDB 136                       // bf16 elements per smem row (128 + 8 pad)
#define ROWB (LDB * 2)                // 272 bytes per row
#define TILE_BYTES (128 * ROWB)       // 34816
#define A_HI_OFF 0
#define A_LO_OFF (TILE_BYTES)
#define W_HI_OFF (2 * TILE_BYTES)
#define W_LO_OFF (3 * TILE_BYTES)
#define GEMM_SMEM_TOTAL (4 * TILE_BYTES)   // 139264 bytes

__global__ __launch_bounds__(256)
void gemm_relu_hmma_kernel(const float* __restrict__ h,
                           const float* __restrict__ Wp,
                           int N)
{
    extern __shared__ char smem[];
    const uint32_t sbase = smem_to_u32(smem);
    const int tid  = threadIdx.x;
    const int lane = tid & 31;
    const int wid  = tid >> 5;
    const int warp_m = wid & 1;       // 0..1 -> 64-row slab
    const int warp_n = wid >> 1;      // 0..3 -> 32-col slab
    const int rowBase = blockIdx.x * 128;

    // ---- stage h tile (hi/lo split) ----
    {
        const int r     = tid >> 1;            // 0..127
        const int cbase = (tid & 1) * 64;      // float offset within row
        const int gr    = rowBase + r;
        const float4* hsrc = reinterpret_cast<const float4*>(
            h + (size_t)gr * DIM + cbase);
        char* dhi = smem + A_HI_OFF + r * ROWB + cbase * 2;
        char* dlo = smem + A_LO_OFF + r * ROWB + cbase * 2;
        #pragma unroll
        for (int q = 0; q < 16; q++) {
            float4 v = (gr < N) ? hsrc[q] : make_float4(0.f, 0.f, 0.f, 0.f);
            float rx, ry, rz, rw;
            uint32_t h0 = pack_bf16_hi(v.x, v.y, rx, ry);
            uint32_t h1 = pack_bf16_hi(v.z, v.w, rz, rw);
            *reinterpret_cast<uint2*>(dhi + q * 8) = make_uint2(h0, h1);
            *reinterpret_cast<uint2*>(dlo + q * 8) =
                make_uint2(pack_bf16(rx, ry), pack_bf16(rz, rw));
        }
        // ---- stage W tile (hi/lo split), layout [out][k] ----
        const float4* wsrc = reinterpret_cast<const float4*>(
            Wp + (size_t)r * DIM + cbase);
        char* whi = smem + W_HI_OFF + r * ROWB + cbase * 2;
        char* wlo = smem + W_LO_OFF + r * ROWB + cbase * 2;
        #pragma unroll
        for (int q = 0; q < 16; q++) {
            float4 v = wsrc[q];
            float rx, ry, rz, rw;
            uint32_t h0 = pack_bf16_hi(v.x, v.y, rx, ry);
            uint32_t h1 = pack_bf16_hi(v.z, v.w, rz, rw);
            *reinterpret_cast<uint2*>(whi + q * 8) = make_uint2(h0, h1);
            *reinterpret_cast<uint2*>(wlo + q * 8) =
                make_uint2(pack_bf16(rx, ry), pack_bf16(rz, rw));
        }
    }
    __syncthreads();

    // ---- accumulate: 3 passes x 8 k-steps x (4m x 4n) HMMA ----
    float acc[4][4][4];
    #pragma unroll
    for (int mi = 0; mi < 4; mi++)
        #pragma unroll
        for (int ni = 0; ni < 4; ni++)
            #pragma unroll
            for (int r = 0; r < 4; r++)
                acc[mi][ni][r] = 0.0f;

    const int lrow = lane & 15;               // ldmatrix row within 16
    const int lk8  = (lane >> 4) << 3;        // 0 or 8 (k-half)

    #pragma unroll
    for (int p = 0; p < 3; p++) {
        const uint32_t aBase = sbase + (p == 2 ? A_LO_OFF : A_HI_OFF);
        const uint32_t bBase = sbase + (p == 1 ? W_LO_OFF : W_HI_OFF);
        #pragma unroll
        for (int ks = 0; ks < 8; ks++) {
            const int k0 = ks * 16;
            uint32_t a[4][4];
            #pragma unroll
            for (int mi = 0; mi < 4; mi++) {
                uint32_t addr = aBase
                    + (uint32_t)(warp_m * 64 + mi * 16 + lrow) * ROWB
                    + (uint32_t)(k0 + lk8) * 2;
                LDMATRIX_X4(a[mi][0], a[mi][1], a[mi][2], a[mi][3], addr);
            }
            uint32_t b[4][2];
            #pragma unroll
            for (int nj = 0; nj < 2; nj++) {
                uint32_t addr = bBase
                    + (uint32_t)(warp_n * 32 + nj * 16 + lrow) * ROWB
                    + (uint32_t)(k0 + lk8) * 2;
                uint32_t m0, m1, m2, m3;
                LDMATRIX_X4(m0, m1, m2, m3, addr);
                b[nj * 2 + 0][0] = m0;   // rows n0..7,  k0..7
                b[nj * 2 + 1][0] = m1;   // rows n8..15, k0..7
                b[nj * 2 + 0][1] = m2;   // rows n0..7,  k8..15
                b[nj * 2 + 1][1] = m3;   // rows n8..15, k8..15
            }
            #pragma unroll
            for (int mi = 0; mi < 4; mi++)
                #pragma unroll
                for (int ni = 0; ni < 4; ni++)
                    MMA_BF16(acc[mi][ni], a[mi], b[ni]);
        }
    }

    // ---- epilogue: ReLU + store to g_proj ----
    const int erow = lane >> 2;               // 0..7
    const int ecol = (lane & 3) * 2;
    #pragma unroll
    for (int mi = 0; mi < 4; mi++) {
        const int row0 = rowBase + warp_m * 64 + mi * 16 + erow;
        #pragma unroll
        for (int ni = 0; ni < 4; ni++) {
            const int col = warp_n * 32 + ni * 8 + ecol;
            if (row0 < N) {
                float2 v;
                v.x = fmaxf(acc[mi][ni][0], 0.0f);
                v.y = fmaxf(acc[mi][ni][1], 0.0f);
                *reinterpret_cast<float2*>(g_proj + (size_t)row0 * DIM + col) = v;
            }
            if (row0 + 8 < N) {
                float2 v;
                v.x = fmaxf(acc[mi][ni][2], 0.0f);
                v.y = fmaxf(acc[mi][ni][3], 0.0f);
                *reinterpret_cast<float2*>(g_proj + (size_t)(row0 + 8) * DIM + col) = v;
            }
        }
    }
}

// ---------------------------------------------------------------------------
// Kernel 2: out[dst[e]] += proj[src[e]]   (warp per edge, red.v4.f32)
// ---------------------------------------------------------------------------
__global__ __launch_bounds__(256)
void scatter_kernel(const int* __restrict__ src,
                    const int* __restrict__ dst,
                    float* __restrict__ out,
                    int E)
{
    int gtid = blockIdx.x * blockDim.x + threadIdx.x;
    int e    = gtid >> 5;
    int lane = gtid & 31;
    if (e >= E) return;

    int s = src[e];
    int d = dst[e];

    const float4 v = *reinterpret_cast<const float4*>(
        g_proj + (size_t)s * DIM + lane * 4);
    float* p = out + (size_t)d * DIM + lane * 4;

    asm volatile("red.global.add.v4.f32 [%0], {%1, %2, %3, %4};"
                 :: "l"(p), "f"(v.x), "f"(v.y), "f"(v.z), "f"(v.w)
                 : "memory");
}

// ---------------------------------------------------------------------------
// Launch
// ---------------------------------------------------------------------------
extern "C" void kernel_launch(void* const* d_in, const int* in_sizes, int n_in,
                              void* d_out, int out_size)
{
    const float* h   = (const float*)d_in[0];
    const float* W   = (const float*)d_in[1];
    const int*   src = (const int*)d_in[2];
    const int*   dst = (const int*)d_in[3];
    float*       out = (float*)d_out;

    const int N = in_sizes[0] / DIM;
    const int E = in_sizes[2];

    static bool attrDone = false;
    if (!attrDone) {
        cudaFuncSetAttribute(gemm_relu_hmma_kernel,
                             cudaFuncAttributeMaxDynamicSharedMemorySize,
                             GEMM_SMEM_TOTAL);
        attrDone = true;
    }

    // out is poisoned; zero it (graph-capturable memset node)
    cudaMemsetAsync(out, 0, (size_t)out_size * sizeof(float), 0);

    // GEMM + ReLU into g_proj (HMMA, split bf16)
    int gemmBlocks = (N + 127) / 128;
    gemm_relu_hmma_kernel<<<gemmBlocks, 256, GEMM_SMEM_TOTAL>>>(h, W, N);

    // Edge scatter: one warp per edge
    long long totalThreads = (long long)E * 32;
    int scatterBlocks = (int)((totalThreads + 255) / 256);
    scatter_kernel<<<scatterBlocks, 256>>>(src, dst, out, E);
}

// round 5
// speedup vs baseline: 1.3186x; 1.0058x over previous
#include <cuda_runtime.h>
#include <cuda_bf16.h>
#include <cstdint>

#define DIM        128
#define MAX_NODES  100000
#define MAX_EDGES  800000

// ---------------------------------------------------------------------------
// Static device scratch (no allocations allowed)
// ---------------------------------------------------------------------------
__device__ float    g_proj[(size_t)MAX_NODES * DIM];   // relu(h @ W^T)
__device__ uint32_t g_Whi[DIM * DIM / 2];               // bf16x2 [n][k/2], hi
__device__ uint32_t g_Wlo[DIM * DIM / 2];               // bf16x2 [n][k/2], lo
__device__ int      g_cnt[MAX_NODES];                   // degree, then cursor
__device__ int      g_off[MAX_NODES + 1];               // CSR offsets (by dst)
__device__ int      g_bsum[128];                        // scan block sums
__device__ int      g_esrc[MAX_EDGES];                  // src grouped by dst

// ---------------------------------------------------------------------------
// helpers
// ---------------------------------------------------------------------------
__device__ __forceinline__ uint32_t smem_to_u32(const void* smem_ptr) {
    uint32_t addr;
    asm("{ .reg .u64 tmp; cvta.to.shared.u64 tmp, %1; cvt.u32.u64 %0, tmp; }"
        : "=r"(addr) : "l"(smem_ptr));
    return addr;
}

#define LDMATRIX_X4(r0, r1, r2, r3, addr) \
    asm volatile("ldmatrix.sync.aligned.m8n8.x4.shared.b16 {%0,%1,%2,%3}, [%4];" \
        : "=r"(r0), "=r"(r1), "=r"(r2), "=r"(r3) : "r"(addr))

#define MMA_BF16(c, a, b) \
    asm volatile("mma.sync.aligned.m16n8k16.row.col.f32.bf16.bf16.f32 " \
        "{%0,%1,%2,%3}, {%4,%5,%6,%7}, {%8,%9}, {%0,%1,%2,%3};" \
        : "+f"((c)[0]), "+f"((c)[1]), "+f"((c)[2]), "+f"((c)[3]) \
        : "r"((a)[0]), "r"((a)[1]), "r"((a)[2]), "r"((a)[3]), \
          "r"((b)[0]), "r"((b)[1]))

__device__ __forceinline__ uint32_t pack_bf16_hi(float a, float b,
                                                 float& ra, float& rb) {
    __nv_bfloat16 ha = __float2bfloat16(a);
    __nv_bfloat16 hb = __float2bfloat16(b);
    ra = a - __bfloat162float(ha);
    rb = b - __bfloat162float(hb);
    return ((uint32_t)__bfloat16_as_ushort(hb) << 16) | __bfloat16_as_ushort(ha);
}
__device__ __forceinline__ uint32_t pack_bf16(float a, float b) {
    return ((uint32_t)__bfloat16_as_ushort(__float2bfloat16(b)) << 16)
         | __bfloat16_as_ushort(__float2bfloat16(a));
}

// ---------------------------------------------------------------------------
// W precompute: split W[n][k] fp32 -> bf16 hi/lo packed pairs [n][k/2]
// ---------------------------------------------------------------------------
__global__ void wprep_kernel(const float* __restrict__ W) {
    int idx = blockIdx.x * blockDim.x + threadIdx.x;      // 0..8191
    if (idx >= DIM * DIM / 2) return;
    int n  = idx >> 6;
    int kp = idx & 63;
    float2 w = *reinterpret_cast<const float2*>(W + (size_t)n * DIM + kp * 2);
    float r0, r1;
    g_Whi[idx] = pack_bf16_hi(w.x, w.y, r0, r1);
    g_Wlo[idx] = pack_bf16(r0, r1);
}

// ---------------------------------------------------------------------------
// CSR build: histogram -> scan -> fill
// ---------------------------------------------------------------------------
__global__ void hist_kernel(const int* __restrict__ dst, int E) {
    int e = blockIdx.x * blockDim.x + threadIdx.x;
    if (e < E) atomicAdd(&g_cnt[dst[e]], 1);
}

#define SCAN_BLK 1024
__global__ void scan_reduce_kernel(int N) {
    __shared__ int sdata[256];
    const int t    = threadIdx.x;
    const int base = blockIdx.x * SCAN_BLK;
    int s = 0;
    #pragma unroll
    for (int q = 0; q < 4; q++) {
        int i = base + t * 4 + q;
        if (i < N) s += g_cnt[i];
    }
    sdata[t] = s;
    __syncthreads();
    #pragma unroll
    for (int o = 128; o > 0; o >>= 1) {
        if (t < o) sdata[t] += sdata[t + o];
        __syncthreads();
    }
    if (t == 0) g_bsum[blockIdx.x] = sdata[0];
}

__global__ void scan_write_kernel(int N, int E) {
    __shared__ int ssum[256];
    __shared__ int sb[128];
    __shared__ int sbase;
    const int b = blockIdx.x, t = threadIdx.x;
    if (t < gridDim.x && t < 128) sb[t] = g_bsum[t];
    __syncthreads();
    if (t == 0) {
        int a = 0;
        for (int j = 0; j < b; j++) a += sb[j];
        sbase = a;
        if (b == 0) g_off[N] = E;
    }
    const int base = b * SCAN_BLK;
    int v[4];
    int local = 0;
    #pragma unroll
    for (int q = 0; q < 4; q++) {
        int i = base + t * 4 + q;
        v[q] = (i < N) ? g_cnt[i] : 0;
        local += v[q];
    }
    ssum[t] = local;
    __syncthreads();
    // inclusive Hillis-Steele over 256 thread sums
    for (int o = 1; o < 256; o <<= 1) {
        int x = (t >= o) ? ssum[t - o] : 0;
        __syncthreads();
        ssum[t] += x;
        __syncthreads();
    }
    int excl = sbase + ssum[t] - local;
    #pragma unroll
    for (int q = 0; q < 4; q++) {
        int i = base + t * 4 + q;
        if (i < N) { g_off[i] = excl; g_cnt[i] = excl; }   // g_cnt becomes cursor
        excl += v[q];
    }
}

__global__ void fill_kernel(const int* __restrict__ src,
                            const int* __restrict__ dst, int E) {
    int e = blockIdx.x * blockDim.x + threadIdx.x;
    if (e < E) {
        int pos = atomicAdd(&g_cnt[dst[e]], 1);
        g_esrc[pos] = src[e];
    }
}

// ---------------------------------------------------------------------------
// GEMM: proj = relu(h @ W^T), split-bf16 HMMA, A in smem, B from global (L1-hot)
//   CTA: 128 rows x 128 out x 128 k, 8 warps = 2(m) x 4(n), warp tile 64x32.
// ---------------------------------------------------------------------------
#define LDB 136
#define ROWB (LDB * 2)
#define TILEB (128 * ROWB)         // 34816
#define A_HI_OFF 0
#define A_LO_OFF TILEB
#define GEMM_SMEM (2 * TILEB)      // 69632 -> 2 CTAs/SM

__global__ __launch_bounds__(256, 2)
void gemm_relu_hmma_kernel(const float* __restrict__ h, int N)
{
    extern __shared__ char smem[];
    const uint32_t sbase = smem_to_u32(smem);
    const int tid  = threadIdx.x;
    const int lane = tid & 31;
    const int wid  = tid >> 5;
    const int warp_m = wid & 1;
    const int warp_n = wid >> 1;
    const int rowBase = blockIdx.x * 128;

    // ---- stage h tile (hi/lo split) ----
    {
        const int r     = tid >> 1;
        const int cbase = (tid & 1) * 64;
        const int gr    = rowBase + r;
        const float4* hsrc = reinterpret_cast<const float4*>(
            h + (size_t)gr * DIM + cbase);
        char* dhi = smem + A_HI_OFF + r * ROWB + cbase * 2;
        char* dlo = smem + A_LO_OFF + r * ROWB + cbase * 2;
        #pragma unroll
        for (int q = 0; q < 16; q++) {
            float4 v = (gr < N) ? hsrc[q] : make_float4(0.f, 0.f, 0.f, 0.f);
            float rx, ry, rz, rw;
            uint32_t h0 = pack_bf16_hi(v.x, v.y, rx, ry);
            uint32_t h1 = pack_bf16_hi(v.z, v.w, rz, rw);
            *reinterpret_cast<uint2*>(dhi + q * 8) = make_uint2(h0, h1);
            *reinterpret_cast<uint2*>(dlo + q * 8) =
                make_uint2(pack_bf16(rx, ry), pack_bf16(rz, rw));
        }
    }
    __syncthreads();

    float acc[4][4][4];
    #pragma unroll
    for (int mi = 0; mi < 4; mi++)
        #pragma unroll
        for (int ni = 0; ni < 4; ni++)
            #pragma unroll
            for (int r = 0; r < 4; r++)
                acc[mi][ni][r] = 0.0f;

    const int lrow = lane & 15;
    const int lk8  = (lane >> 4) << 3;
    // B fragment row pointers: lane holds n = warp_n*32 + ni*8 + lane/4,
    // packed-pair column (lane&3); b0 = wrow[ks*8], b1 = wrow[ks*8+4]
    const uint32_t wrowoff =
        (uint32_t)(warp_n * 32 + (lane >> 2)) * 64 + (lane & 3);

    #pragma unroll
    for (int p = 0; p < 3; p++) {
        const uint32_t aBase = sbase + (p == 2 ? A_LO_OFF : A_HI_OFF);
        const uint32_t* __restrict__ Wg = (p == 1) ? g_Wlo : g_Whi;
        #pragma unroll
        for (int ks = 0; ks < 8; ks++) {
            const int k0 = ks * 16;
            uint32_t a[4][4];
            #pragma unroll
            for (int mi = 0; mi < 4; mi++) {
                uint32_t addr = aBase
                    + (uint32_t)(warp_m * 64 + mi * 16 + lrow) * ROWB
                    + (uint32_t)(k0 + lk8) * 2;
                LDMATRIX_X4(a[mi][0], a[mi][1], a[mi][2], a[mi][3], addr);
            }
            #pragma unroll
            for (int ni = 0; ni < 4; ni++) {
                const uint32_t* wrow = Wg + wrowoff + (uint32_t)ni * 8 * 64;
                uint32_t b[2];
                b[0] = wrow[ks * 8];
                b[1] = wrow[ks * 8 + 4];
                #pragma unroll
                for (int mi = 0; mi < 4; mi++)
                    MMA_BF16(acc[mi][ni], a[mi], b);
            }
        }
    }

    // ---- epilogue: ReLU + store ----
    const int erow = lane >> 2;
    const int ecol = (lane & 3) * 2;
    #pragma unroll
    for (int mi = 0; mi < 4; mi++) {
        const int row0 = rowBase + warp_m * 64 + mi * 16 + erow;
        #pragma unroll
        for (int ni = 0; ni < 4; ni++) {
            const int col = warp_n * 32 + ni * 8 + ecol;
            if (row0 < N) {
                float2 v;
                v.x = fmaxf(acc[mi][ni][0], 0.0f);
                v.y = fmaxf(acc[mi][ni][1], 0.0f);
                *reinterpret_cast<float2*>(g_proj + (size_t)row0 * DIM + col) = v;
            }
            if (row0 + 8 < N) {
                float2 v;
                v.x = fmaxf(acc[mi][ni][2], 0.0f);
                v.y = fmaxf(acc[mi][ni][3], 0.0f);
                *reinterpret_cast<float2*>(g_proj + (size_t)(row0 + 8) * DIM + col) = v;
            }
        }
    }
}

// ---------------------------------------------------------------------------
// Gather: out[d] = sum over CSR bucket of proj[src] (no atomics, full cover)
// One warp per dst node; lane owns one float4 column slice.
// ---------------------------------------------------------------------------
__global__ __launch_bounds__(256)
void gather_kernel(float* __restrict__ out, int N)
{
    int gtid = blockIdx.x * blockDim.x + threadIdx.x;
    int d    = gtid >> 5;
    int lane = gtid & 31;
    if (d >= N) return;

    const int start = g_off[d];
    const int end   = g_off[d + 1];

    float4 acc = make_float4(0.f, 0.f, 0.f, 0.f);
    int i = start;
    for (; i + 1 < end; i += 2) {
        int s0 = g_esrc[i];
        int s1 = g_esrc[i + 1];
        float4 v0 = *reinterpret_cast<const float4*>(
            g_proj + (size_t)s0 * DIM + lane * 4);
        float4 v1 = *reinterpret_cast<const float4*>(
            g_proj + (size_t)s1 * DIM + lane * 4);
        acc.x += v0.x + v1.x;
        acc.y += v0.y + v1.y;
        acc.z += v0.z + v1.z;
        acc.w += v0.w + v1.w;
    }
    if (i < end) {
        int s0 = g_esrc[i];
        float4 v0 = *reinterpret_cast<const float4*>(
            g_proj + (size_t)s0 * DIM + lane * 4);
        acc.x += v0.x; acc.y += v0.y; acc.z += v0.z; acc.w += v0.w;
    }
    *reinterpret_cast<float4*>(out + (size_t)d * DIM + lane * 4) = acc;
}

// ---------------------------------------------------------------------------
// Launch
// ---------------------------------------------------------------------------
extern "C" void kernel_launch(void* const* d_in, const int* in_sizes, int n_in,
                              void* d_out, int out_size)
{
    const float* h   = (const float*)d_in[0];
    const float* W   = (const float*)d_in[1];
    const int*   src = (const int*)d_in[2];
    const int*   dst = (const int*)d_in[3];
    float*       out = (float*)d_out;

    const int N = in_sizes[0] / DIM;
    const int E = in_sizes[2];

    cudaFuncSetAttribute(gemm_relu_hmma_kernel,
                         cudaFuncAttributeMaxDynamicSharedMemorySize,
                         GEMM_SMEM);

    // zero degree counters (memset node; out itself needs no zeroing now)
    void* cntPtr = nullptr;
    cudaGetSymbolAddress(&cntPtr, g_cnt);
    cudaMemsetAsync(cntPtr, 0, (size_t)N * sizeof(int), 0);

    // W split precompute (once per call, trivial)
    wprep_kernel<<<32, 256>>>(W);

    // CSR build by dst
    hist_kernel<<<(E + 255) / 256, 256>>>(dst, E);
    const int NB = (N + SCAN_BLK - 1) / SCAN_BLK;          // 98 for N=100000
    scan_reduce_kernel<<<NB, 256>>>(N);
    scan_write_kernel<<<NB, 256>>>(N, E);
    fill_kernel<<<(E + 255) / 256, 256>>>(src, dst, E);

    // GEMM + ReLU into g_proj
    gemm_relu_hmma_kernel<<<(N + 127) / 128, 256, GEMM_SMEM>>>(h, N);

    // Gather per dst node (writes every out element; no memset needed)
    long long totalThreads = (long long)N * 32;
    gather_kernel<<<(int)((totalThreads + 255) / 256), 256>>>(out, N);
}

// round 6
// speedup vs baseline: 1.3902x; 1.0543x over previous
#include <cuda_runtime.h>
#include <cuda_bf16.h>
#include <cuda_fp16.h>
#include <cstdint>

#define DIM        128
#define MAX_NODES  100000
#define MAX_EDGES  800000

// ---------------------------------------------------------------------------
// Static device scratch (no allocations allowed)
// ---------------------------------------------------------------------------
__device__ __half   g_projh[(size_t)MAX_NODES * DIM];   // relu(h @ W^T), fp16
__device__ uint32_t g_Whi[DIM * DIM / 2];               // bf16x2 [n][k/2], hi
__device__ uint32_t g_Wlo[DIM * DIM / 2];               // bf16x2 [n][k/2], lo
__device__ int      g_cnt[MAX_NODES];                   // degree, then cursor
__device__ int      g_off[MAX_NODES + 1];               // CSR offsets (by dst)
__device__ int      g_bsum[128];                        // scan block sums
__device__ int      g_esrc[MAX_EDGES];                  // src grouped by dst

// ---------------------------------------------------------------------------
// helpers
// ---------------------------------------------------------------------------
__device__ __forceinline__ uint32_t smem_to_u32(const void* smem_ptr) {
    uint32_t addr;
    asm("{ .reg .u64 tmp; cvta.to.shared.u64 tmp, %1; cvt.u32.u64 %0, tmp; }"
        : "=r"(addr) : "l"(smem_ptr));
    return addr;
}

#define LDMATRIX_X4(r0, r1, r2, r3, addr) \
    asm volatile("ldmatrix.sync.aligned.m8n8.x4.shared.b16 {%0,%1,%2,%3}, [%4];" \
        : "=r"(r0), "=r"(r1), "=r"(r2), "=r"(r3) : "r"(addr))

#define MMA_BF16(c, a, b) \
    asm volatile("mma.sync.aligned.m16n8k16.row.col.f32.bf16.bf16.f32 " \
        "{%0,%1,%2,%3}, {%4,%5,%6,%7}, {%8,%9}, {%0,%1,%2,%3};" \
        : "+f"((c)[0]), "+f"((c)[1]), "+f"((c)[2]), "+f"((c)[3]) \
        : "r"((a)[0]), "r"((a)[1]), "r"((a)[2]), "r"((a)[3]), \
          "r"((b)[0]), "r"((b)[1]))

__device__ __forceinline__ uint32_t pack_bf16_hi(float a, float b,
                                                 float& ra, float& rb) {
    __nv_bfloat16 ha = __float2bfloat16(a);
    __nv_bfloat16 hb = __float2bfloat16(b);
    ra = a - __bfloat162float(ha);
    rb = b - __bfloat162float(hb);
    return ((uint32_t)__bfloat16_as_ushort(hb) << 16) | __bfloat16_as_ushort(ha);
}
__device__ __forceinline__ uint32_t pack_bf16(float a, float b) {
    return ((uint32_t)__bfloat16_as_ushort(__float2bfloat16(b)) << 16)
         | __bfloat16_as_ushort(__float2bfloat16(a));
}

// ---------------------------------------------------------------------------
// W precompute: split W[n][k] fp32 -> bf16 hi/lo packed pairs [n][k/2]
// ---------------------------------------------------------------------------
__global__ void wprep_kernel(const float* __restrict__ W) {
    int idx = blockIdx.x * blockDim.x + threadIdx.x;      // 0..8191
    if (idx >= DIM * DIM / 2) return;
    int n  = idx >> 6;
    int kp = idx & 63;
    float2 w = *reinterpret_cast<const float2*>(W + (size_t)n * DIM + kp * 2);
    float r0, r1;
    g_Whi[idx] = pack_bf16_hi(w.x, w.y, r0, r1);
    g_Wlo[idx] = pack_bf16(r0, r1);
}

// ---------------------------------------------------------------------------
// CSR build: histogram -> scan -> fill
// ---------------------------------------------------------------------------
__global__ void hist_kernel(const int* __restrict__ dst, int E) {
    int e = blockIdx.x * blockDim.x + threadIdx.x;
    if (e < E) atomicAdd(&g_cnt[dst[e]], 1);
}

#define SCAN_BLK 1024
__global__ void scan_reduce_kernel(int N) {
    __shared__ int sdata[256];
    const int t    = threadIdx.x;
    const int base = blockIdx.x * SCAN_BLK;
    int s = 0;
    #pragma unroll
    for (int q = 0; q < 4; q++) {
        int i = base + t * 4 + q;
        if (i < N) s += g_cnt[i];
    }
    sdata[t] = s;
    __syncthreads();
    #pragma unroll
    for (int o = 128; o > 0; o >>= 1) {
        if (t < o) sdata[t] += sdata[t + o];
        __syncthreads();
    }
    if (t == 0) g_bsum[blockIdx.x] = sdata[0];
}

__global__ void scan_write_kernel(int N, int E) {
    __shared__ int ssum[256];
    __shared__ int sb[128];
    __shared__ int sbase;
    const int b = blockIdx.x, t = threadIdx.x;
    if (t < gridDim.x && t < 128) sb[t] = g_bsum[t];
    __syncthreads();
    if (t == 0) {
        int a = 0;
        for (int j = 0; j < b; j++) a += sb[j];
        sbase = a;
        if (b == 0) g_off[N] = E;
    }
    const int base = b * SCAN_BLK;
    int v[4];
    int local = 0;
    #pragma unroll
    for (int q = 0; q < 4; q++) {
        int i = base + t * 4 + q;
        v[q] = (i < N) ? g_cnt[i] : 0;
        local += v[q];
    }
    ssum[t] = local;
    __syncthreads();
    for (int o = 1; o < 256; o <<= 1) {
        int x = (t >= o) ? ssum[t - o] : 0;
        __syncthreads();
        ssum[t] += x;
        __syncthreads();
    }
    int excl = sbase + ssum[t] - local;
    #pragma unroll
    for (int q = 0; q < 4; q++) {
        int i = base + t * 4 + q;
        if (i < N) { g_off[i] = excl; g_cnt[i] = excl; }   // g_cnt becomes cursor
        excl += v[q];
    }
}

__global__ void fill_kernel(const int* __restrict__ src,
                            const int* __restrict__ dst, int E) {
    int e = blockIdx.x * blockDim.x + threadIdx.x;
    if (e < E) {
        int pos = atomicAdd(&g_cnt[dst[e]], 1);
        g_esrc[pos] = src[e];
    }
}

// ---------------------------------------------------------------------------
// GEMM: proj = relu(h @ W^T) -> fp16, split-bf16 HMMA, A in smem, B from global
//   CTA: 128 rows x 128 out x 128 k, 8 warps = 2(m) x 4(n), warp tile 64x32.
// ---------------------------------------------------------------------------
#define LDB 136
#define ROWB (LDB * 2)
#define TILEB (128 * ROWB)         // 34816
#define A_HI_OFF 0
#define A_LO_OFF TILEB
#define GEMM_SMEM (2 * TILEB)      // 69632 -> 2 CTAs/SM

__global__ __launch_bounds__(256, 2)
void gemm_relu_hmma_kernel(const float* __restrict__ h, int N)
{
    extern __shared__ char smem[];
    const uint32_t sbase = smem_to_u32(smem);
    const int tid  = threadIdx.x;
    const int lane = tid & 31;
    const int wid  = tid >> 5;
    const int warp_m = wid & 1;
    const int warp_n = wid >> 1;
    const int rowBase = blockIdx.x * 128;

    // ---- stage h tile (hi/lo split) ----
    {
        const int r     = tid >> 1;
        const int cbase = (tid & 1) * 64;
        const int gr    = rowBase + r;
        const float4* hsrc = reinterpret_cast<const float4*>(
            h + (size_t)gr * DIM + cbase);
        char* dhi = smem + A_HI_OFF + r * ROWB + cbase * 2;
        char* dlo = smem + A_LO_OFF + r * ROWB + cbase * 2;
        #pragma unroll
        for (int q = 0; q < 16; q++) {
            float4 v = (gr < N) ? hsrc[q] : make_float4(0.f, 0.f, 0.f, 0.f);
            float rx, ry, rz, rw;
            uint32_t h0 = pack_bf16_hi(v.x, v.y, rx, ry);
            uint32_t h1 = pack_bf16_hi(v.z, v.w, rz, rw);
            *reinterpret_cast<uint2*>(dhi + q * 8) = make_uint2(h0, h1);
            *reinterpret_cast<uint2*>(dlo + q * 8) =
                make_uint2(pack_bf16(rx, ry), pack_bf16(rz, rw));
        }
    }
    __syncthreads();

    float acc[4][4][4];
    #pragma unroll
    for (int mi = 0; mi < 4; mi++)
        #pragma unroll
        for (int ni = 0; ni < 4; ni++)
            #pragma unroll
            for (int r = 0; r < 4; r++)
                acc[mi][ni][r] = 0.0f;

    const int lrow = lane & 15;
    const int lk8  = (lane >> 4) << 3;
    const uint32_t wrowoff =
        (uint32_t)(warp_n * 32 + (lane >> 2)) * 64 + (lane & 3);

    #pragma unroll
    for (int p = 0; p < 3; p++) {
        const uint32_t aBase = sbase + (p == 2 ? A_LO_OFF : A_HI_OFF);
        const uint32_t* __restrict__ Wg = (p == 1) ? g_Wlo : g_Whi;
        #pragma unroll
        for (int ks = 0; ks < 8; ks++) {
            const int k0 = ks * 16;
            uint32_t a[4][4];
            #pragma unroll
            for (int mi = 0; mi < 4; mi++) {
                uint32_t addr = aBase
                    + (uint32_t)(warp_m * 64 + mi * 16 + lrow) * ROWB
                    + (uint32_t)(k0 + lk8) * 2;
                LDMATRIX_X4(a[mi][0], a[mi][1], a[mi][2], a[mi][3], addr);
            }
            #pragma unroll
            for (int ni = 0; ni < 4; ni++) {
                const uint32_t* wrow = Wg + wrowoff + (uint32_t)ni * 8 * 64;
                uint32_t b[2];
                b[0] = wrow[ks * 8];
                b[1] = wrow[ks * 8 + 4];
                #pragma unroll
                for (int mi = 0; mi < 4; mi++)
                    MMA_BF16(acc[mi][ni], a[mi], b);
            }
        }
    }

    // ---- epilogue: ReLU + fp16 store ----
    const int erow = lane >> 2;
    const int ecol = (lane & 3) * 2;
    #pragma unroll
    for (int mi = 0; mi < 4; mi++) {
        const int row0 = rowBase + warp_m * 64 + mi * 16 + erow;
        #pragma unroll
        for (int ni = 0; ni < 4; ni++) {
            const int col = warp_n * 32 + ni * 8 + ecol;
            if (row0 < N) {
                __half2 hv = __floats2half2_rn(fmaxf(acc[mi][ni][0], 0.0f),
                                               fmaxf(acc[mi][ni][1], 0.0f));
                *reinterpret_cast<__half2*>(
                    g_projh + (size_t)row0 * DIM + col) = hv;
            }
            if (row0 + 8 < N) {
                __half2 hv = __floats2half2_rn(fmaxf(acc[mi][ni][2], 0.0f),
                                               fmaxf(acc[mi][ni][3], 0.0f));
                *reinterpret_cast<__half2*>(
                    g_projh + (size_t)(row0 + 8) * DIM + col) = hv;
            }
        }
    }
}

// ---------------------------------------------------------------------------
// Gather: out[d] = sum over CSR bucket of projh[src]
// 16 lanes per dst (2 dsts per warp); lane owns 8 cols (uint4 = 8 fp16).
// Unrolled x4 for MLP; fp32 accumulation.
// ---------------------------------------------------------------------------
__device__ __forceinline__ void acc_row(float acc[8], uint4 r) {
    const __half2* hp = reinterpret_cast<const __half2*>(&r);
    #pragma unroll
    for (int j = 0; j < 4; j++) {
        float2 f = __half22float2(hp[j]);
        acc[j * 2 + 0] += f.x;
        acc[j * 2 + 1] += f.y;
    }
}

__global__ __launch_bounds__(256)
void gather_kernel(float* __restrict__ out, int N)
{
    int gtid = blockIdx.x * blockDim.x + threadIdx.x;
    int d    = gtid >> 4;            // 16 lanes per dst
    int l16  = gtid & 15;
    if (d >= N) return;

    const int start = g_off[d];
    const int end   = g_off[d + 1];

    float acc[8];
    #pragma unroll
    for (int j = 0; j < 8; j++) acc[j] = 0.0f;

    const uint4* projv = reinterpret_cast<const uint4*>(g_projh) + l16;

    int i = start;
    for (; i + 3 < end; i += 4) {
        int s0 = g_esrc[i + 0];
        int s1 = g_esrc[i + 1];
        int s2 = g_esrc[i + 2];
        int s3 = g_esrc[i + 3];
        uint4 r0 = projv[(size_t)s0 * 16];
        uint4 r1 = projv[(size_t)s1 * 16];
        uint4 r2 = projv[(size_t)s2 * 16];
        uint4 r3 = projv[(size_t)s3 * 16];
        acc_row(acc, r0);
        acc_row(acc, r1);
        acc_row(acc, r2);
        acc_row(acc, r3);
    }
    for (; i < end; i++) {
        int s0 = g_esrc[i];
        uint4 r0 = projv[(size_t)s0 * 16];
        acc_row(acc, r0);
    }

    float* op = out + (size_t)d * DIM + l16 * 8;
    *reinterpret_cast<float4*>(op)     = make_float4(acc[0], acc[1], acc[2], acc[3]);
    *reinterpret_cast<float4*>(op + 4) = make_float4(acc[4], acc[5], acc[6], acc[7]);
}

// ---------------------------------------------------------------------------
// Launch
// ---------------------------------------------------------------------------
extern "C" void kernel_launch(void* const* d_in, const int* in_sizes, int n_in,
                              void* d_out, int out_size)
{
    const float* h   = (const float*)d_in[0];
    const float* W   = (const float*)d_in[1];
    const int*   src = (const int*)d_in[2];
    const int*   dst = (const int*)d_in[3];
    float*       out = (float*)d_out;

    const int N = in_sizes[0] / DIM;
    const int E = in_sizes[2];

    cudaFuncSetAttribute(gemm_relu_hmma_kernel,
                         cudaFuncAttributeMaxDynamicSharedMemorySize,
                         GEMM_SMEM);

    // zero degree counters
    void* cntPtr = nullptr;
    cudaGetSymbolAddress(&cntPtr, g_cnt);
    cudaMemsetAsync(cntPtr, 0, (size_t)N * sizeof(int), 0);

    // W split precompute
    wprep_kernel<<<32, 256>>>(W);

    // CSR build by dst
    hist_kernel<<<(E + 255) / 256, 256>>>(dst, E);
    const int NB = (N + SCAN_BLK - 1) / SCAN_BLK;
    scan_reduce_kernel<<<NB, 256>>>(N);
    scan_write_kernel<<<NB, 256>>>(N, E);
    fill_kernel<<<(E + 255) / 256, 256>>>(src, dst, E);

    // GEMM + ReLU into g_projh (fp16)
    gemm_relu_hmma_kernel<<<(N + 127) / 128, 256, GEMM_SMEM>>>(h, N);

    // Gather per dst node (16 lanes per node)
    long long totalThreads = (long long)N * 16;
    gather_kernel<<<(int)((totalThreads + 255) / 256), 256>>>(out, N);
}

// round 7
// speedup vs baseline: 2.1199x; 1.5249x over previous
#include <cuda_runtime.h>
#include <cuda_bf16.h>
#include <cuda_fp16.h>
#include <cstdint>

#define DIM        128
#define MAX_NODES  100000
#define MAX_EDGES  800000

// ---------------------------------------------------------------------------
// Static device scratch (no allocations allowed)
// ---------------------------------------------------------------------------
__device__ __half   g_projh[(size_t)MAX_NODES * DIM];   // relu(h @ W^T), fp16
__device__ uint32_t g_Whi[DIM * DIM / 2];               // fp16x2 [n][k/2], hi
__device__ uint32_t g_Wlo[DIM * DIM / 2];               // fp16x2 [n][k/2], residual
__device__ int      g_cnt[MAX_NODES];                   // degree, then cursor
__device__ int      g_off[MAX_NODES + 1];               // CSR offsets (by dst)
__device__ int      g_bsum[128];                        // scan block sums
__device__ int      g_esrc[MAX_EDGES];                  // src grouped by dst

// ---------------------------------------------------------------------------
// helpers
// ---------------------------------------------------------------------------
__device__ __forceinline__ uint32_t smem_to_u32(const void* smem_ptr) {
    uint32_t addr;
    asm("{ .reg .u64 tmp; cvta.to.shared.u64 tmp, %1; cvt.u32.u64 %0, tmp; }"
        : "=r"(addr) : "l"(smem_ptr));
    return addr;
}

#define LDMATRIX_X4(r0, r1, r2, r3, addr) \
    asm volatile("ldmatrix.sync.aligned.m8n8.x4.shared.b16 {%0,%1,%2,%3}, [%4];" \
        : "=r"(r0), "=r"(r1), "=r"(r2), "=r"(r3) : "r"(addr))

#define MMA_F16(c, a, b) \
    asm volatile("mma.sync.aligned.m16n8k16.row.col.f32.f16.f16.f32 " \
        "{%0,%1,%2,%3}, {%4,%5,%6,%7}, {%8,%9}, {%0,%1,%2,%3};" \
        : "+f"((c)[0]), "+f"((c)[1]), "+f"((c)[2]), "+f"((c)[3]) \
        : "r"((a)[0]), "r"((a)[1]), "r"((a)[2]), "r"((a)[3]), \
          "r"((b)[0]), "r"((b)[1]))

__device__ __forceinline__ uint32_t pack_h2(float a, float b) {
    __half2 h = __floats2half2_rn(a, b);
    return *reinterpret_cast<uint32_t*>(&h);
}

// ---------------------------------------------------------------------------
// W precompute: W[n][k] fp32 -> fp16 hi + fp16 residual, packed pairs [n][k/2]
// ---------------------------------------------------------------------------
__global__ void wprep_kernel(const float* __restrict__ W) {
    int idx = blockIdx.x * blockDim.x + threadIdx.x;      // 0..8191
    if (idx >= DIM * DIM / 2) return;
    int n  = idx >> 6;
    int kp = idx & 63;
    float2 w = *reinterpret_cast<const float2*>(W + (size_t)n * DIM + kp * 2);
    __half h0 = __float2half_rn(w.x);
    __half h1 = __float2half_rn(w.y);
    float r0 = w.x - __half2float(h0);
    float r1 = w.y - __half2float(h1);
    __half2 hi = __halves2half2(h0, h1);
    g_Whi[idx] = *reinterpret_cast<uint32_t*>(&hi);
    g_Wlo[idx] = pack_h2(r0, r1);
}

// ---------------------------------------------------------------------------
// CSR build: histogram -> scan -> fill
// ---------------------------------------------------------------------------
__global__ void hist_kernel(const int* __restrict__ dst, int E) {
    int e = blockIdx.x * blockDim.x + threadIdx.x;
    if (e < E) atomicAdd(&g_cnt[dst[e]], 1);
}

#define SCAN_BLK 1024
__global__ void scan_reduce_kernel(int N) {
    __shared__ int sdata[256];
    const int t    = threadIdx.x;
    const int base = blockIdx.x * SCAN_BLK;
    int s = 0;
    #pragma unroll
    for (int q = 0; q < 4; q++) {
        int i = base + t * 4 + q;
        if (i < N) s += g_cnt[i];
    }
    sdata[t] = s;
    __syncthreads();
    #pragma unroll
    for (int o = 128; o > 0; o >>= 1) {
        if (t < o) sdata[t] += sdata[t + o];
        __syncthreads();
    }
    if (t == 0) g_bsum[blockIdx.x] = sdata[0];
}

__global__ void scan_write_kernel(int N, int E) {
    __shared__ int ssum[256];
    __shared__ int sb[128];
    __shared__ int sbase;
    const int b = blockIdx.x, t = threadIdx.x;
    if (t < gridDim.x && t < 128) sb[t] = g_bsum[t];
    __syncthreads();
    if (t == 0) {
        int a = 0;
        for (int j = 0; j < b; j++) a += sb[j];
        sbase = a;
        if (b == 0) g_off[N] = E;
    }
    const int base = b * SCAN_BLK;
    int v[4];
    int local = 0;
    #pragma unroll
    for (int q = 0; q < 4; q++) {
        int i = base + t * 4 + q;
        v[q] = (i < N) ? g_cnt[i] : 0;
        local += v[q];
    }
    ssum[t] = local;
    __syncthreads();
    for (int o = 1; o < 256; o <<= 1) {
        int x = (t >= o) ? ssum[t - o] : 0;
        __syncthreads();
        ssum[t] += x;
        __syncthreads();
    }
    int excl = sbase + ssum[t] - local;
    #pragma unroll
    for (int q = 0; q < 4; q++) {
        int i = base + t * 4 + q;
        if (i < N) { g_off[i] = excl; g_cnt[i] = excl; }   // g_cnt becomes cursor
        excl += v[q];
    }
}

__global__ void fill_kernel(const int* __restrict__ src,
                            const int* __restrict__ dst, int E) {
    int e = blockIdx.x * blockDim.x + threadIdx.x;
    if (e < E) {
        int pos = atomicAdd(&g_cnt[dst[e]], 1);
        g_esrc[pos] = src[e];
    }
}

// ---------------------------------------------------------------------------
// GEMM: proj = relu(h @ W^T) -> fp16. 2-pass fp16 HMMA:
//   pass0: h16 * W_hi, pass1: h16 * W_lo (residual). fp32 accum.
//   CTA: 128 rows x 128 out x 128 k, 8 warps = 2(m) x 4(n), warp tile 64x32.
//   A (h16) in padded smem; B fragments straight from global (L1-hot, 32KB).
// ---------------------------------------------------------------------------
#define LDB 136
#define ROWB (LDB * 2)
#define GEMM_SMEM (128 * ROWB)     // 34816 bytes -> 2 CTAs/SM (reg-limited)

__global__ __launch_bounds__(256, 2)
void gemm_relu_hmma_kernel(const float* __restrict__ h, int N)
{
    extern __shared__ char smem[];
    const uint32_t sbase = smem_to_u32(smem);
    const int tid  = threadIdx.x;
    const int lane = tid & 31;
    const int wid  = tid >> 5;
    const int warp_m = wid & 1;
    const int warp_n = wid >> 1;
    const int rowBase = blockIdx.x * 128;

    // ---- stage h tile as fp16 ----
    {
        const int r     = tid >> 1;
        const int cbase = (tid & 1) * 64;
        const int gr    = rowBase + r;
        const float4* hsrc = reinterpret_cast<const float4*>(
            h + (size_t)gr * DIM + cbase);
        char* dst16 = smem + r * ROWB + cbase * 2;
        #pragma unroll
        for (int q = 0; q < 16; q++) {
            float4 v = (gr < N) ? hsrc[q] : make_float4(0.f, 0.f, 0.f, 0.f);
            *reinterpret_cast<uint2*>(dst16 + q * 8) =
                make_uint2(pack_h2(v.x, v.y), pack_h2(v.z, v.w));
        }
    }
    __syncthreads();

    float acc[4][4][4];
    #pragma unroll
    for (int mi = 0; mi < 4; mi++)
        #pragma unroll
        for (int ni = 0; ni < 4; ni++)
            #pragma unroll
            for (int r = 0; r < 4; r++)
                acc[mi][ni][r] = 0.0f;

    const int lrow = lane & 15;
    const int lk8  = (lane >> 4) << 3;
    const uint32_t wrowoff =
        (uint32_t)(warp_n * 32 + (lane >> 2)) * 64 + (lane & 3);

    #pragma unroll
    for (int p = 0; p < 2; p++) {
        const uint32_t* __restrict__ Wg = (p == 0) ? g_Whi : g_Wlo;
        #pragma unroll
        for (int ks = 0; ks < 8; ks++) {
            const int k0 = ks * 16;
            uint32_t a[4][4];
            #pragma unroll
            for (int mi = 0; mi < 4; mi++) {
                uint32_t addr = sbase
                    + (uint32_t)(warp_m * 64 + mi * 16 + lrow) * ROWB
                    + (uint32_t)(k0 + lk8) * 2;
                LDMATRIX_X4(a[mi][0], a[mi][1], a[mi][2], a[mi][3], addr);
            }
            #pragma unroll
            for (int ni = 0; ni < 4; ni++) {
                const uint32_t* wrow = Wg + wrowoff + (uint32_t)ni * 8 * 64;
                uint32_t b[2];
                b[0] = wrow[ks * 8];
                b[1] = wrow[ks * 8 + 4];
                #pragma unroll
                for (int mi = 0; mi < 4; mi++)
                    MMA_F16(acc[mi][ni], a[mi], b);
            }
        }
    }

    // ---- epilogue: ReLU + fp16 store ----
    const int erow = lane >> 2;
    const int ecol = (lane & 3) * 2;
    #pragma unroll
    for (int mi = 0; mi < 4; mi++) {
        const int row0 = rowBase + warp_m * 64 + mi * 16 + erow;
        #pragma unroll
        for (int ni = 0; ni < 4; ni++) {
            const int col = warp_n * 32 + ni * 8 + ecol;
            if (row0 < N) {
                __half2 hv = __floats2half2_rn(fmaxf(acc[mi][ni][0], 0.0f),
                                               fmaxf(acc[mi][ni][1], 0.0f));
                *reinterpret_cast<__half2*>(
                    g_projh + (size_t)row0 * DIM + col) = hv;
            }
            if (row0 + 8 < N) {
                __half2 hv = __floats2half2_rn(fmaxf(acc[mi][ni][2], 0.0f),
                                               fmaxf(acc[mi][ni][3], 0.0f));
                *reinterpret_cast<__half2*>(
                    g_projh + (size_t)(row0 + 8) * DIM + col) = hv;
            }
        }
    }
}

// ---------------------------------------------------------------------------
// Gather: out[d] = sum over CSR bucket of projh[src]
// 16 lanes per dst (2 dsts per warp); lane owns 8 cols (uint4 = 8 fp16).
// ---------------------------------------------------------------------------
__device__ __forceinline__ void acc_row(float acc[8], uint4 r) {
    const __half2* hp = reinterpret_cast<const __half2*>(&r);
    #pragma unroll
    for (int j = 0; j < 4; j++) {
        float2 f = __half22float2(hp[j]);
        acc[j * 2 + 0] += f.x;
        acc[j * 2 + 1] += f.y;
    }
}

__global__ __launch_bounds__(256)
void gather_kernel(float* __restrict__ out, int N)
{
    int gtid = blockIdx.x * blockDim.x + threadIdx.x;
    int d    = gtid >> 4;            // 16 lanes per dst
    int l16  = gtid & 15;
    if (d >= N) return;

    const int start = g_off[d];
    const int end   = g_off[d + 1];

    float acc[8];
    #pragma unroll
    for (int j = 0; j < 8; j++) acc[j] = 0.0f;

    const uint4* projv = reinterpret_cast<const uint4*>(g_projh) + l16;

    int i = start;
    for (; i + 3 < end; i += 4) {
        int s0 = g_esrc[i + 0];
        int s1 = g_esrc[i + 1];
        int s2 = g_esrc[i + 2];
        int s3 = g_esrc[i + 3];
        uint4 r0 = projv[(size_t)s0 * 16];
        uint4 r1 = projv[(size_t)s1 * 16];
        uint4 r2 = projv[(size_t)s2 * 16];
        uint4 r3 = projv[(size_t)s3 * 16];
        acc_row(acc, r0);
        acc_row(acc, r1);
        acc_row(acc, r2);
        acc_row(acc, r3);
    }
    for (; i < end; i++) {
        int s0 = g_esrc[i];
        uint4 r0 = projv[(size_t)s0 * 16];
        acc_row(acc, r0);
    }

    float* op = out + (size_t)d * DIM + l16 * 8;
    *reinterpret_cast<float4*>(op)     = make_float4(acc[0], acc[1], acc[2], acc[3]);
    *reinterpret_cast<float4*>(op + 4) = make_float4(acc[4], acc[5], acc[6], acc[7]);
}

// ---------------------------------------------------------------------------
// Launch: fork GEMM onto a side stream so it overlaps the CSR build.
// ---------------------------------------------------------------------------
extern "C" void kernel_launch(void* const* d_in, const int* in_sizes, int n_in,
                              void* d_out, int out_size)
{
    const float* h   = (const float*)d_in[0];
    const float* W   = (const float*)d_in[1];
    const int*   src = (const int*)d_in[2];
    const int*   dst = (const int*)d_in[3];
    float*       out = (float*)d_out;

    const int N = in_sizes[0] / DIM;
    const int E = in_sizes[2];

    static cudaStream_t s2 = nullptr;
    static cudaEvent_t evFork = nullptr, evJoin = nullptr;
    if (!s2) {
        cudaStreamCreateWithFlags(&s2, cudaStreamNonBlocking);
        cudaEventCreateWithFlags(&evFork, cudaEventDisableTiming);
        cudaEventCreateWithFlags(&evJoin, cudaEventDisableTiming);
        cudaFuncSetAttribute(gemm_relu_hmma_kernel,
                             cudaFuncAttributeMaxDynamicSharedMemorySize,
                             GEMM_SMEM);
    }

    // zero degree counters
    void* cntPtr = nullptr;
    cudaGetSymbolAddress(&cntPtr, g_cnt);
    cudaMemsetAsync(cntPtr, 0, (size_t)N * sizeof(int), 0);

    // W split precompute (needed by GEMM)
    wprep_kernel<<<32, 256>>>(W);

    // ---- fork: GEMM on s2, CSR build stays on stream 0 ----
    cudaEventRecord(evFork, 0);
    cudaStreamWaitEvent(s2, evFork, 0);

    gemm_relu_hmma_kernel<<<(N + 127) / 128, 256, GEMM_SMEM, s2>>>(h, N);

    hist_kernel<<<(E + 255) / 256, 256>>>(dst, E);
    const int NB = (N + SCAN_BLK - 1) / SCAN_BLK;
    scan_reduce_kernel<<<NB, 256>>>(N);
    scan_write_kernel<<<NB, 256>>>(N, E);
    fill_kernel<<<(E + 255) / 256, 256>>>(src, dst, E);

    // ---- join ----
    cudaEventRecord(evJoin, s2);
    cudaStreamWaitEvent(0, evJoin, 0);

    // Gather per dst node (16 lanes per node)
    long long totalThreads = (long long)N * 16;
    gather_kernel<<<(int)((totalThreads + 255) / 256), 256>>>(out, N);
}